// round 10
// baseline (speedup 1.0000x reference)
#include <cuda_runtime.h>
#include <cstdint>

// Problem constants
#define BB   16384
#define AA   32
#define UU   64
#define SS   2048
#define EE   32
#define HYPD 64
#define HHD  4
#define NN   288      // H*HYP + E = 256 + 32
#define KKD  2048

#define NB3  (BB/8)   // attn kernel blocks (8 rows per block)

// ---------------- scratch (device globals; no allocation allowed) -------------
__device__ float g_Wcat[NN * KKD];      // packed+tf32-rounded weights [n][k]
__device__ float g_bias[NN];            // concatenated biases
__device__ float g_H1[BB * NN];         // relu(states@Wcat + bias)
__device__ float g_C[HHD * HYPD * UU];  // C[h][k][u] = sum_e sel_w2[h][k][e]*key_w[h][u][e]
__device__ float g_M[BB * 256];         // M[b][h*64+u]
__device__ float g_part[NB3 * 5];       // per-block partials: [mag, ent0..3]

__device__ __forceinline__ uint32_t f2tf(float f) {
    uint32_t u; asm("cvt.rna.tf32.f32 %0, %1;" : "=r"(u) : "f"(f)); return u;
}

__device__ __forceinline__ float warpsum(float v) {
    #pragma unroll
    for (int o = 16; o; o >>= 1) v += __shfl_xor_sync(0xffffffffu, v, o);
    return v;
}
__device__ __forceinline__ float warpmax(float v) {
    #pragma unroll
    for (int o = 16; o; o >>= 1) v = fmaxf(v, __shfl_xor_sync(0xffffffffu, v, o));
    return v;
}

__device__ __forceinline__ uint32_t smem_u32(const void* p) {
    return (uint32_t)__cvta_generic_to_shared(p);
}
__device__ __forceinline__ void cp_async16(uint32_t dst, const void* src) {
    asm volatile("cp.async.ca.shared.global [%0], [%1], 16;\n" :: "r"(dst), "l"(src));
}
__device__ __forceinline__ void cp_commit() {
    asm volatile("cp.async.commit_group;\n");
}
template <int N>
__device__ __forceinline__ void cp_wait() {
    asm volatile("cp.async.wait_group %0;\n" :: "n"(N));
}

// ---------------- kernel 0a: coalesced weight pack via smem transpose ---------
__global__ __launch_bounds__(256)
void pack_transpose(const float* __restrict__ sel_w1,
                    const float* __restrict__ v_w1) {
    __shared__ float tile[32][33];
    const int z  = blockIdx.z;
    const int k0 = blockIdx.x * 32;
    const int j0 = blockIdx.y * 32;
    const int tx = threadIdx.x, ty = threadIdx.y;  // 32 x 8

    if (z == 4 && blockIdx.y != 0) return;

    if (z < 4) {
        const float* src = sel_w1 + (size_t)z * SS * HYPD;
        #pragma unroll
        for (int i = 0; i < 32; i += 8)
            tile[ty + i][tx] = src[(size_t)(k0 + ty + i) * HYPD + j0 + tx];
        __syncthreads();
        #pragma unroll
        for (int i = 0; i < 32; i += 8)
            g_Wcat[(size_t)(z * 64 + j0 + ty + i) * KKD + k0 + tx] =
                __uint_as_float(f2tf(tile[tx][ty + i]));
    } else {
        #pragma unroll
        for (int i = 0; i < 32; i += 8)
            tile[ty + i][tx] = v_w1[(size_t)(k0 + ty + i) * EE + tx];
        __syncthreads();
        #pragma unroll
        for (int i = 0; i < 32; i += 8)
            g_Wcat[(size_t)(256 + ty + i) * KKD + k0 + tx] =
                __uint_as_float(f2tf(tile[tx][ty + i]));
    }
}

// ---------------- kernel 0b: C[h] = sel_w2[h] @ key_w[h]^T, plus bias ---------
__global__ __launch_bounds__(256)
void pack_c(const float* __restrict__ sel_w2, const float* __restrict__ key_w,
            const float* __restrict__ sel_b1, const float* __restrict__ v_b1) {
    __shared__ float sw2[HYPD * EE];   // [k][e]
    __shared__ float kw[UU * EE];      // [u][e]
    const int h = blockIdx.x;
    const int t = threadIdx.x;

    if (h == 0) {  // fold bias pack into block 0
        for (int i = t; i < NN; i += 256)
            g_bias[i] = (i < 256) ? sel_b1[i] : v_b1[i - 256];
    }

    for (int i = t; i < HYPD * EE; i += 256) sw2[i] = sel_w2[h * HYPD * EE + i];
    for (int i = t; i < UU * EE; i += 256)   kw[i]  = key_w[h * UU * EE + i];
    __syncthreads();

    for (int o = t; o < HYPD * UU; o += 256) {
        int k = o >> 6, u = o & 63;
        float s = 0.f;
        #pragma unroll
        for (int e = 0; e < EE; e++) s += sw2[k * EE + e] * kw[u * EE + e];
        g_C[h * HYPD * UU + o] = s;
    }
}

// ---------------- kernel 1: GEMM [16384,2048]x[2048,288] tf32 mma.sync --------
// BM=64, 256 threads, double-buffered cp.async; 2 CTAs co-resident per SM so
// one CTA's loads/barriers overlap the other's mma stream.
#define BM 64
#define BKC 32
#define AST 36
#define BST 36
#define STAGES 2
#define A_STG (BM * AST)    // 2304 floats
#define B_STG (NN * BST)    // 10368 floats
#define STG_FLOATS (A_STG + B_STG)             // 12672
#define GEMM_SMEM (STAGES * STG_FLOATS * 4)    // 101376 bytes

__global__ __launch_bounds__(256, 2)
void gemm_kernel(const float* __restrict__ states) {
    extern __shared__ float sm[];
    float* As = sm;                          // [STAGES][BM][AST]
    float* Bs = sm + STAGES * A_STG;         // [STAGES][NN][BST]

    const int t    = threadIdx.x;
    const int lane = t & 31;
    const int warp = t >> 5;               // 0..7
    const int wM   = warp & 1;             // 2 warps along M
    const int wN   = warp >> 1;            // 4 warps along N
    const int grp  = lane >> 2;            // 0..7
    const int tid4 = lane & 3;             // 0..3
    const int rowBase = blockIdx.x * BM;

    float acc[2][9][4];
    #pragma unroll
    for (int i = 0; i < 2; i++)
        #pragma unroll
        for (int j = 0; j < 9; j++)
            #pragma unroll
            for (int c = 0; c < 4; c++) acc[i][j][c] = 0.f;

    // stage loader: A 512 chunks of 16B (2/thread), B 2304 chunks (9/thread)
    auto load_stage = [&](int s, int k0) {
        {
            uint32_t dstA = smem_u32(As + s * A_STG);
            #pragma unroll
            for (int r = 0; r < 2; r++) {
                int c = t + r * 256;            // 0..511
                int arow = c >> 3;
                int koff = (c & 7) * 4;
                cp_async16(dstA + (uint32_t)(arow * AST + koff) * 4,
                           states + (size_t)(rowBase + arow) * KKD + k0 + koff);
            }
        }
        {
            uint32_t dstB = smem_u32(Bs + s * B_STG);
            #pragma unroll
            for (int r = 0; r < 9; r++) {
                int c = t + r * 256;            // 0..2303
                int n = c >> 3;
                int koff = (c & 7) * 4;
                cp_async16(dstB + (uint32_t)(n * BST + koff) * 4,
                           g_Wcat + (size_t)n * KKD + k0 + koff);
            }
        }
        cp_commit();
    };

    load_stage(0, 0);

    const int NITER = KKD / BKC;           // 64
    for (int it = 0; it < NITER; ++it) {
        const int cur = it & 1;
        cp_wait<0>();          // stage cur ready
        __syncthreads();       // all threads done with stage cur^1 (prev compute)

        if (it + 1 < NITER)
            load_stage(cur ^ 1, (it + 1) * BKC);   // flies during compute below

        const float* Ab = As + cur * A_STG;
        const float* Bb = Bs + cur * B_STG;
        #pragma unroll
        for (int kk = 0; kk < BKC; kk += 8) {
            uint32_t af[2][4];
            #pragma unroll
            for (int mt = 0; mt < 2; mt++) {
                int m0 = wM * 32 + mt * 16 + grp;
                af[mt][0] = f2tf(Ab[m0 * AST + kk + tid4]);
                af[mt][1] = f2tf(Ab[(m0 + 8) * AST + kk + tid4]);
                af[mt][2] = f2tf(Ab[m0 * AST + kk + tid4 + 4]);
                af[mt][3] = f2tf(Ab[(m0 + 8) * AST + kk + tid4 + 4]);
            }
            #pragma unroll
            for (int nt = 0; nt < 9; nt++) {
                int n0 = wN * 72 + nt * 8 + grp;
                uint32_t b0 = __float_as_uint(Bb[n0 * BST + kk + tid4]);
                uint32_t b1 = __float_as_uint(Bb[n0 * BST + kk + tid4 + 4]);
                #pragma unroll
                for (int mt = 0; mt < 2; mt++) {
                    asm volatile(
                        "mma.sync.aligned.m16n8k8.row.col.f32.tf32.tf32.f32 "
                        "{%0,%1,%2,%3}, {%4,%5,%6,%7}, {%8,%9}, {%0,%1,%2,%3};\n"
                        : "+f"(acc[mt][nt][0]), "+f"(acc[mt][nt][1]),
                          "+f"(acc[mt][nt][2]), "+f"(acc[mt][nt][3])
                        : "r"(af[mt][0]), "r"(af[mt][1]),
                          "r"(af[mt][2]), "r"(af[mt][3]),
                        "r"(b0), "r"(b1));
                }
            }
        }
    }

    // ---- epilogue: bias + relu -> g_H1 ----
    #pragma unroll
    for (int mt = 0; mt < 2; mt++) {
        int r0 = rowBase + wM * 32 + mt * 16 + grp;
        #pragma unroll
        for (int nt = 0; nt < 9; nt++) {
            int c0 = wN * 72 + nt * 8 + tid4 * 2;
            float b0 = g_bias[c0], b1 = g_bias[c0 + 1];
            g_H1[(size_t)r0 * NN + c0]           = fmaxf(acc[mt][nt][0] + b0, 0.f);
            g_H1[(size_t)r0 * NN + c0 + 1]       = fmaxf(acc[mt][nt][1] + b1, 0.f);
            g_H1[(size_t)(r0 + 8) * NN + c0]     = fmaxf(acc[mt][nt][2] + b0, 0.f);
            g_H1[(size_t)(r0 + 8) * NN + c0 + 1] = fmaxf(acc[mt][nt][3] + b1, 0.f);
        }
    }
}

// ---------------- kernel 1.5: M = H1 @ blockdiag(C), plus v output -----------
#define MROWS 32
#define HSTM 289
#define MST  257
__global__ __launch_bounds__(256)
void m_kernel(const float* __restrict__ v_w2,
              const float* __restrict__ v_b2,
              float* __restrict__ out) {
    extern __shared__ float smm[];
    float* Cs   = smm;                       // [4][64][64] = 16384
    float* hsm  = Cs + HHD * HYPD * UU;      // [32][289]
    float* Ms   = hsm + MROWS * HSTM;        // [32][257]
    float* vw2s = Ms + MROWS * MST;          // [32]

    const int t = threadIdx.x, lane = t & 31, w = t >> 5;   // 8 warps
    const int b0 = blockIdx.x * MROWS;

    for (int i = t; i < HHD * HYPD * UU; i += 256) Cs[i] = g_C[i];
    for (int i = t; i < MROWS * NN; i += 256) {
        int r = i / NN, c = i - r * NN;
        hsm[r * HSTM + c] = g_H1[(size_t)(b0 + r) * NN + c];
    }
    if (t < 32) vw2s[t] = v_w2[t];
    __syncthreads();

    {
        const int h  = w >> 1;
        const int u0 = (w & 1) * 32;
        float acc[32];
        #pragma unroll
        for (int j = 0; j < 32; j++) acc[j] = 0.f;

        const float* hr = hsm + lane * HSTM + h * 64;
        const float* Cb = Cs + h * HYPD * UU + u0;
        #pragma unroll 4
        for (int k = 0; k < 64; k++) {
            float hval = hr[k];
            const float4* cp4 = (const float4*)(Cb + k * UU);
            #pragma unroll
            for (int q = 0; q < 8; q++) {
                float4 cv = cp4[q];
                acc[q * 4 + 0] += hval * cv.x;
                acc[q * 4 + 1] += hval * cv.y;
                acc[q * 4 + 2] += hval * cv.z;
                acc[q * 4 + 3] += hval * cv.w;
            }
        }
        float* mrow = Ms + lane * MST + h * 64 + u0;
        #pragma unroll
        for (int j = 0; j < 32; j++) mrow[j] = acc[j];
    }

    if (t < 32) {
        float s = 0.f;
        const float* hr = hsm + t * HSTM + 256;
        #pragma unroll
        for (int j = 0; j < 32; j++) s += hr[j] * vw2s[j];
        out[(size_t)BB * AA + b0 + t] = s + v_b2[0];
    }
    __syncthreads();

    float* gdst = g_M + (size_t)b0 * 256;
    for (int i = t; i < MROWS * 256; i += 256) {
        int r = i >> 8, c = i & 255;
        gdst[i] = Ms[r * MST + c];
    }
}
#define M_SMEM ((HHD*HYPD*UU + MROWS*HSTM + MROWS*MST + 32) * 4)

// ---------------- kernel 2: logits -> softmax -> outputs ----------------------
__global__ __launch_bounds__(256)
void attn_kernel(const float* __restrict__ states,
                 float* __restrict__ out) {
    __shared__ float spart[8][5];

    const int t = threadIdx.x, lane = t & 31, w = t >> 5;
    const int b = blockIdx.x * 8 + w;

    float m0[4], m1[4];
    const float* mrow = g_M + (size_t)b * 256;
    #pragma unroll
    for (int h = 0; h < 4; h++) {
        m0[h] = mrow[h * 64 + lane];
        m1[h] = mrow[h * 64 + 32 + lane];
    }

    const float* srow = states + (size_t)b * SS;
    float v0[32], v1[32];
    #pragma unroll
    for (int a = 0; a < 32; a++) {
        v0[a] = srow[a * 64 + lane];
        v1[a] = srow[a * 64 + 32 + lane];
    }

    float lg[4];
    #pragma unroll
    for (int h = 0; h < 4; h++) {
        float vals[32];
        #pragma unroll
        for (int a = 0; a < 32; a++)
            vals[a] = v0[a] * m0[h] + v1[a] * m1[h];
        #pragma unroll
        for (int m = 16; m >= 1; m >>= 1) {
            #pragma unroll
            for (int jj = 0; jj < m; jj++) {
                float lo = vals[jj], hi = vals[jj + m];
                float send = (lane & m) ? lo : hi;
                float recv = __shfl_xor_sync(0xffffffffu, send, m);
                vals[jj] = ((lane & m) ? hi : lo) + recv;
            }
        }
        lg[h] = vals[0];
    }

    const float invsq = 0.17677669529663687f;  // 1/sqrt(32)
    float ha = 0.f, mag = 0.f;
    float entp[4];
    #pragma unroll
    for (int h = 0; h < 4; h++) {
        mag += lg[h] * lg[h];
        float z = lg[h] * invsq;
        float mx = warpmax(z);
        float e = __expf(z - mx);
        float ssum = warpsum(e);
        float wgt = e / ssum;
        ha += wgt;
        entp[h] = warpsum(wgt * __logf(wgt + 1e-8f));
    }
    mag = warpsum(mag);

    out[(size_t)b * AA + lane] = ha;  // head_attend

    if (lane == 0) {
        spart[w][0] = mag;
        #pragma unroll
        for (int h = 0; h < 4; h++) spart[w][1 + h] = entp[h];
    }
    __syncthreads();
    if (t == 0) {
        float acc[5] = {0, 0, 0, 0, 0};
        for (int ww = 0; ww < 8; ww++)
            #pragma unroll
            for (int c = 0; c < 5; c++) acc[c] += spart[ww][c];
        #pragma unroll
        for (int c = 0; c < 5; c++) g_part[blockIdx.x * 5 + c] = acc[c];
    }
}

// ---------------- kernel 3: deterministic finalize ----------------------------
__global__ __launch_bounds__(256)
void finalize_kernel(float* __restrict__ out) {
    __shared__ float red[8][5];
    const int t = threadIdx.x, lane = t & 31, w = t >> 5;
    float acc[5] = {0, 0, 0, 0, 0};
    for (int j = t; j < NB3; j += 256) {
        #pragma unroll
        for (int c = 0; c < 5; c++) acc[c] += g_part[j * 5 + c];
    }
    #pragma unroll
    for (int c = 0; c < 5; c++) acc[c] = warpsum(acc[c]);
    if (lane == 0)
        #pragma unroll
        for (int c = 0; c < 5; c++) red[w][c] = acc[c];
    __syncthreads();
    if (t == 0) {
        float fin[5] = {0, 0, 0, 0, 0};
        #pragma unroll
        for (int ww = 0; ww < 8; ww++)
            #pragma unroll
            for (int c = 0; c < 5; c++) fin[c] += red[ww][c];
        out[(size_t)BB * AA + BB] = 1e-3f * fin[0] / (float)((size_t)BB * AA);
        #pragma unroll
        for (int c = 1; c < 5; c++)
            out[(size_t)BB * AA + BB + c] = -fin[c] / (float)BB;
    }
}

// ---------------- launch ------------------------------------------------------
extern "C" void kernel_launch(void* const* d_in, const int* in_sizes, int n_in,
                              void* d_out, int out_size) {
    (void)in_sizes; (void)n_in; (void)out_size;
    // metadata order: agent_qs, states, sel_w1, sel_b1, sel_w2, key_w, v_w1, v_b1, v_w2, v_b2
    const float* states = (const float*)d_in[1];
    const float* sel_w1 = (const float*)d_in[2];
    const float* sel_b1 = (const float*)d_in[3];
    const float* sel_w2 = (const float*)d_in[4];
    const float* key_w  = (const float*)d_in[5];
    const float* v_w1   = (const float*)d_in[6];
    const float* v_b1   = (const float*)d_in[7];
    const float* v_w2   = (const float*)d_in[8];
    const float* v_b2   = (const float*)d_in[9];
    float* out = (float*)d_out;

    cudaFuncSetAttribute(gemm_kernel, cudaFuncAttributeMaxDynamicSharedMemorySize, GEMM_SMEM);
    cudaFuncSetAttribute(m_kernel, cudaFuncAttributeMaxDynamicSharedMemorySize, M_SMEM);

    pack_transpose<<<dim3(SS / 32, 2, 5), dim3(32, 8)>>>(sel_w1, v_w1);
    pack_c<<<HHD, 256>>>(sel_w2, key_w, sel_b1, v_b1);
    gemm_kernel<<<BB / BM, 256, GEMM_SMEM>>>(states);
    m_kernel<<<BB / MROWS, 256, M_SMEM>>>(v_w2, v_b2, out);
    attn_kernel<<<NB3, 256>>>(states, out);
    finalize_kernel<<<1, 256>>>(out);
}

// round 12
// speedup vs baseline: 1.3604x; 1.3604x over previous
#include <cuda_runtime.h>
#include <cstdint>

// Problem constants
#define BB   16384
#define AA   32
#define UU   64
#define SS   2048
#define EE   32
#define HYPD 64
#define HHD  4
#define NN   288      // H*HYP + E = 256 + 32
#define KKD  2048

#define NB3  (BB/8)   // attn kernel blocks (8 rows per block)

// ---------------- scratch (device globals; no allocation allowed) -------------
__device__ float g_Wcat[NN * KKD];      // packed+tf32-rounded weights [n][k]
__device__ float g_bias[NN];            // concatenated biases
__device__ float g_H1[BB * NN];         // relu(states@Wcat + bias)
__device__ float g_C[HHD * HYPD * UU];  // C[h][k][u] = sum_e sel_w2[h][k][e]*key_w[h][u][e]
__device__ float g_M[BB * 256];         // M[b][h*64+u]
__device__ float g_part[NB3 * 5];       // per-block partials: [mag, ent0..3]

__device__ __forceinline__ uint32_t f2tf(float f) {
    uint32_t u; asm("cvt.rna.tf32.f32 %0, %1;" : "=r"(u) : "f"(f)); return u;
}

__device__ __forceinline__ float warpsum(float v) {
    #pragma unroll
    for (int o = 16; o; o >>= 1) v += __shfl_xor_sync(0xffffffffu, v, o);
    return v;
}
__device__ __forceinline__ float warpmax(float v) {
    #pragma unroll
    for (int o = 16; o; o >>= 1) v = fmaxf(v, __shfl_xor_sync(0xffffffffu, v, o));
    return v;
}

__device__ __forceinline__ uint32_t smem_u32(const void* p) {
    return (uint32_t)__cvta_generic_to_shared(p);
}
__device__ __forceinline__ void cp_async16(uint32_t dst, const void* src) {
    asm volatile("cp.async.ca.shared.global [%0], [%1], 16;\n" :: "r"(dst), "l"(src));
}
__device__ __forceinline__ void cp_commit() {
    asm volatile("cp.async.commit_group;\n");
}
template <int N>
__device__ __forceinline__ void cp_wait() {
    asm volatile("cp.async.wait_group %0;\n" :: "n"(N));
}

// ---------------- kernel 0a: coalesced weight pack via smem transpose ---------
__global__ __launch_bounds__(256)
void pack_transpose(const float* __restrict__ sel_w1,
                    const float* __restrict__ v_w1) {
    __shared__ float tile[32][33];
    const int z  = blockIdx.z;
    const int k0 = blockIdx.x * 32;
    const int j0 = blockIdx.y * 32;
    const int tx = threadIdx.x, ty = threadIdx.y;  // 32 x 8

    if (z == 4 && blockIdx.y != 0) return;

    if (z < 4) {
        const float* src = sel_w1 + (size_t)z * SS * HYPD;
        #pragma unroll
        for (int i = 0; i < 32; i += 8)
            tile[ty + i][tx] = src[(size_t)(k0 + ty + i) * HYPD + j0 + tx];
        __syncthreads();
        #pragma unroll
        for (int i = 0; i < 32; i += 8)
            g_Wcat[(size_t)(z * 64 + j0 + ty + i) * KKD + k0 + tx] =
                __uint_as_float(f2tf(tile[tx][ty + i]));
    } else {
        #pragma unroll
        for (int i = 0; i < 32; i += 8)
            tile[ty + i][tx] = v_w1[(size_t)(k0 + ty + i) * EE + tx];
        __syncthreads();
        #pragma unroll
        for (int i = 0; i < 32; i += 8)
            g_Wcat[(size_t)(256 + ty + i) * KKD + k0 + tx] =
                __uint_as_float(f2tf(tile[tx][ty + i]));
    }
}

// ---------------- kernel 0b: C[h] = sel_w2[h] @ key_w[h]^T, plus bias ---------
__global__ __launch_bounds__(256)
void pack_c(const float* __restrict__ sel_w2, const float* __restrict__ key_w,
            const float* __restrict__ sel_b1, const float* __restrict__ v_b1) {
    __shared__ float sw2[HYPD * EE];   // [k][e]
    __shared__ float kw[UU * EE];      // [u][e]
    const int h = blockIdx.x;
    const int t = threadIdx.x;

    if (h == 0) {  // fold bias pack into block 0
        for (int i = t; i < NN; i += 256)
            g_bias[i] = (i < 256) ? sel_b1[i] : v_b1[i - 256];
    }

    for (int i = t; i < HYPD * EE; i += 256) sw2[i] = sel_w2[h * HYPD * EE + i];
    for (int i = t; i < UU * EE; i += 256)   kw[i]  = key_w[h * UU * EE + i];
    __syncthreads();

    for (int o = t; o < HYPD * UU; o += 256) {
        int k = o >> 6, u = o & 63;
        float s = 0.f;
        #pragma unroll
        for (int e = 0; e < EE; e++) s += sw2[k * EE + e] * kw[u * EE + e];
        g_C[h * HYPD * UU + o] = s;
    }
}

// ---------------- kernel 1: GEMM [16384,2048]x[2048,288] tf32, cp.async x3 ----
// (R7 configuration: BM=128, 512 threads, 3-stage — measured 130.8us)
#define BM 128
#define BKC 32
#define AST 36
#define BST 36
#define STAGES 3
#define A_STG (BM * AST)    // 4608 floats
#define B_STG (NN * BST)    // 10368 floats
#define STG_FLOATS (A_STG + B_STG)             // 14976
#define GEMM_SMEM (STAGES * STG_FLOATS * 4)    // 179712 bytes

__global__ __launch_bounds__(512, 1)
void gemm_kernel(const float* __restrict__ states) {
    extern __shared__ float sm[];
    float* As = sm;
    float* Bs = sm + STAGES * A_STG;

    const int t    = threadIdx.x;
    const int lane = t & 31;
    const int warp = t >> 5;
    const int wM   = warp & 3;
    const int wN   = warp >> 2;
    const int grp  = lane >> 2;
    const int tid4 = lane & 3;
    const int rowBase = blockIdx.x * BM;

    float acc[2][9][4];
    #pragma unroll
    for (int i = 0; i < 2; i++)
        #pragma unroll
        for (int j = 0; j < 9; j++)
            #pragma unroll
            for (int c = 0; c < 4; c++) acc[i][j][c] = 0.f;

    auto load_stage = [&](int s, int k0) {
        {
            uint32_t dstA = smem_u32(As + s * A_STG);
            #pragma unroll
            for (int r = 0; r < 2; r++) {
                int c = t + r * 512;
                int arow = c >> 3;
                int koff = (c & 7) * 4;
                cp_async16(dstA + (uint32_t)(arow * AST + koff) * 4,
                           states + (size_t)(rowBase + arow) * KKD + k0 + koff);
            }
        }
        {
            uint32_t dstB = smem_u32(Bs + s * B_STG);
            for (int c = t; c < NN * 8; c += 512) {
                int n = c >> 3;
                int koff = (c & 7) * 4;
                cp_async16(dstB + (uint32_t)(n * BST + koff) * 4,
                           g_Wcat + (size_t)n * KKD + k0 + koff);
            }
        }
        cp_commit();
    };

    load_stage(0, 0);
    load_stage(1, BKC);

    const int NITER = KKD / BKC;           // 64
    for (int it = 0; it < NITER; ++it) {
        const int cur = it % STAGES;
        cp_wait<1>();
        __syncthreads();

        if (it + STAGES - 1 < NITER)
            load_stage((it + 2) % STAGES, (it + 2) * BKC);

        const float* Ab = As + cur * A_STG;
        const float* Bb = Bs + cur * B_STG;
        #pragma unroll
        for (int kk = 0; kk < BKC; kk += 8) {
            uint32_t af[2][4];
            #pragma unroll
            for (int mt = 0; mt < 2; mt++) {
                int m0 = wM * 32 + mt * 16 + grp;
                af[mt][0] = f2tf(Ab[m0 * AST + kk + tid4]);
                af[mt][1] = f2tf(Ab[(m0 + 8) * AST + kk + tid4]);
                af[mt][2] = f2tf(Ab[m0 * AST + kk + tid4 + 4]);
                af[mt][3] = f2tf(Ab[(m0 + 8) * AST + kk + tid4 + 4]);
            }
            #pragma unroll
            for (int nt = 0; nt < 9; nt++) {
                int n0 = wN * 72 + nt * 8 + grp;
                uint32_t b0 = __float_as_uint(Bb[n0 * BST + kk + tid4]);
                uint32_t b1 = __float_as_uint(Bb[n0 * BST + kk + tid4 + 4]);
                #pragma unroll
                for (int mt = 0; mt < 2; mt++) {
                    asm volatile(
                        "mma.sync.aligned.m16n8k8.row.col.f32.tf32.tf32.f32 "
                        "{%0,%1,%2,%3}, {%4,%5,%6,%7}, {%8,%9}, {%0,%1,%2,%3};\n"
                        : "+f"(acc[mt][nt][0]), "+f"(acc[mt][nt][1]),
                          "+f"(acc[mt][nt][2]), "+f"(acc[mt][nt][3])
                        : "r"(af[mt][0]), "r"(af[mt][1]),
                          "r"(af[mt][2]), "r"(af[mt][3]),
                        "r"(b0), "r"(b1));
                }
            }
        }
    }

    #pragma unroll
    for (int mt = 0; mt < 2; mt++) {
        int r0 = rowBase + wM * 32 + mt * 16 + grp;
        #pragma unroll
        for (int nt = 0; nt < 9; nt++) {
            int c0 = wN * 72 + nt * 8 + tid4 * 2;
            float b0 = g_bias[c0], b1 = g_bias[c0 + 1];
            g_H1[(size_t)r0 * NN + c0]           = fmaxf(acc[mt][nt][0] + b0, 0.f);
            g_H1[(size_t)r0 * NN + c0 + 1]       = fmaxf(acc[mt][nt][1] + b1, 0.f);
            g_H1[(size_t)(r0 + 8) * NN + c0]     = fmaxf(acc[mt][nt][2] + b0, 0.f);
            g_H1[(size_t)(r0 + 8) * NN + c0 + 1] = fmaxf(acc[mt][nt][3] + b1, 0.f);
        }
    }
}

// ---------------- kernel 1.5: M = H1 @ blockdiag(C), register-resident C ------
// Thread t owns output column o=t (h=t>>6, u=t&63); C[h][:,u] lives in 64 regs.
// H1 rows streamed through an 18KB cp.async double buffer -> high occupancy.
#define MR   64    // rows per block  -> 256 blocks
#define MCH  8     // rows per chunk
#define NCHK (MR / MCH)
__global__ __launch_bounds__(256)
void m_kernel(const float* __restrict__ v_w2,
              const float* __restrict__ v_b2,
              float* __restrict__ out) {
    __shared__ float hs[2][MCH][NN];   // 2*8*288*4 = 18432 B
    __shared__ float vw2s[32];

    const int t = threadIdx.x;
    const int b0 = blockIdx.x * MR;
    const int h = t >> 6;              // 0..3
    const int u = t & 63;

    // C column -> registers (coalesced: lanes span consecutive u)
    float creg[64];
    {
        const float* cp = g_C + h * HYPD * UU + u;
        #pragma unroll
        for (int k = 0; k < 64; k++) creg[k] = cp[k * UU];
    }
    if (t < 32) vw2s[t] = v_w2[t];
    const float vb2 = v_b2[0];

    auto load_chunk = [&](int s, int r0) {
        uint32_t dst = smem_u32(&hs[s][0][0]);
        // 8 rows x 72 float4 = 576 chunks
        for (int c = t; c < MCH * 72; c += 256) {
            int r = c / 72, q = c - r * 72;
            cp_async16(dst + (uint32_t)(r * NN + q * 4) * 4,
                       g_H1 + (size_t)(b0 + r0 + r) * NN + q * 4);
        }
        cp_commit();
    };

    load_chunk(0, 0);
    __syncthreads();   // vw2s visible

    for (int ch = 0; ch < NCHK; ch++) {
        const int cur = ch & 1;
        cp_wait<0>();
        __syncthreads();

        if (ch + 1 < NCHK) load_chunk(cur ^ 1, (ch + 1) * MCH);

        // 8 rows in 2 groups of 4 (ILP across rows; hs reads are broadcasts)
        #pragma unroll
        for (int g = 0; g < 2; g++) {
            const float* h0 = &hs[cur][g * 4 + 0][h * 64];
            const float* h1 = &hs[cur][g * 4 + 1][h * 64];
            const float* h2 = &hs[cur][g * 4 + 2][h * 64];
            const float* h3 = &hs[cur][g * 4 + 3][h * 64];
            float a0 = 0.f, a1 = 0.f, a2 = 0.f, a3 = 0.f;
            #pragma unroll
            for (int k = 0; k < 64; k++) {
                float cv = creg[k];
                a0 += h0[k] * cv;
                a1 += h1[k] * cv;
                a2 += h2[k] * cv;
                a3 += h3[k] * cv;
            }
            const size_t r = (size_t)(b0 + ch * MCH + g * 4);
            g_M[(r + 0) * 256 + t] = a0;
            g_M[(r + 1) * 256 + t] = a1;
            g_M[(r + 2) * 256 + t] = a2;
            g_M[(r + 3) * 256 + t] = a3;
        }

        // v outputs for these 8 rows
        if (t < MCH) {
            float s = 0.f;
            const float* hr = &hs[cur][t][256];
            #pragma unroll
            for (int j = 0; j < 32; j++) s += hr[j] * vw2s[j];
            out[(size_t)BB * AA + b0 + ch * MCH + t] = s + vb2;
        }
    }
}

// ---------------- kernel 2: logits -> softmax -> outputs ----------------------
__global__ __launch_bounds__(256)
void attn_kernel(const float* __restrict__ states,
                 float* __restrict__ out) {
    __shared__ float spart[8][5];

    const int t = threadIdx.x, lane = t & 31, w = t >> 5;
    const int b = blockIdx.x * 8 + w;

    float m0[4], m1[4];
    const float* mrow = g_M + (size_t)b * 256;
    #pragma unroll
    for (int h = 0; h < 4; h++) {
        m0[h] = mrow[h * 64 + lane];
        m1[h] = mrow[h * 64 + 32 + lane];
    }

    const float* srow = states + (size_t)b * SS;
    float v0[32], v1[32];
    #pragma unroll
    for (int a = 0; a < 32; a++) {
        v0[a] = srow[a * 64 + lane];
        v1[a] = srow[a * 64 + 32 + lane];
    }

    float lg[4];
    #pragma unroll
    for (int h = 0; h < 4; h++) {
        float vals[32];
        #pragma unroll
        for (int a = 0; a < 32; a++)
            vals[a] = v0[a] * m0[h] + v1[a] * m1[h];
        #pragma unroll
        for (int m = 16; m >= 1; m >>= 1) {
            #pragma unroll
            for (int jj = 0; jj < m; jj++) {
                float lo = vals[jj], hi = vals[jj + m];
                float send = (lane & m) ? lo : hi;
                float recv = __shfl_xor_sync(0xffffffffu, send, m);
                vals[jj] = ((lane & m) ? hi : lo) + recv;
            }
        }
        lg[h] = vals[0];
    }

    const float invsq = 0.17677669529663687f;  // 1/sqrt(32)
    float ha = 0.f, mag = 0.f;
    float entp[4];
    #pragma unroll
    for (int h = 0; h < 4; h++) {
        mag += lg[h] * lg[h];
        float z = lg[h] * invsq;
        float mx = warpmax(z);
        float e = __expf(z - mx);
        float ssum = warpsum(e);
        float wgt = e / ssum;
        ha += wgt;
        entp[h] = warpsum(wgt * __logf(wgt + 1e-8f));
    }
    mag = warpsum(mag);

    out[(size_t)b * AA + lane] = ha;  // head_attend

    if (lane == 0) {
        spart[w][0] = mag;
        #pragma unroll
        for (int h = 0; h < 4; h++) spart[w][1 + h] = entp[h];
    }
    __syncthreads();
    if (t == 0) {
        float acc[5] = {0, 0, 0, 0, 0};
        for (int ww = 0; ww < 8; ww++)
            #pragma unroll
            for (int c = 0; c < 5; c++) acc[c] += spart[ww][c];
        #pragma unroll
        for (int c = 0; c < 5; c++) g_part[blockIdx.x * 5 + c] = acc[c];
    }
}

// ---------------- kernel 3: deterministic finalize ----------------------------
__global__ __launch_bounds__(256)
void finalize_kernel(float* __restrict__ out) {
    __shared__ float red[8][5];
    const int t = threadIdx.x, lane = t & 31, w = t >> 5;
    float acc[5] = {0, 0, 0, 0, 0};
    for (int j = t; j < NB3; j += 256) {
        #pragma unroll
        for (int c = 0; c < 5; c++) acc[c] += g_part[j * 5 + c];
    }
    #pragma unroll
    for (int c = 0; c < 5; c++) acc[c] = warpsum(acc[c]);
    if (lane == 0)
        #pragma unroll
        for (int c = 0; c < 5; c++) red[w][c] = acc[c];
    __syncthreads();
    if (t == 0) {
        float fin[5] = {0, 0, 0, 0, 0};
        #pragma unroll
        for (int ww = 0; ww < 8; ww++)
            #pragma unroll
            for (int c = 0; c < 5; c++) fin[c] += red[ww][c];
        out[(size_t)BB * AA + BB] = 1e-3f * fin[0] / (float)((size_t)BB * AA);
        #pragma unroll
        for (int c = 1; c < 5; c++)
            out[(size_t)BB * AA + BB + c] = -fin[c] / (float)BB;
    }
}

// ---------------- launch ------------------------------------------------------
extern "C" void kernel_launch(void* const* d_in, const int* in_sizes, int n_in,
                              void* d_out, int out_size) {
    (void)in_sizes; (void)n_in; (void)out_size;
    // metadata order: agent_qs, states, sel_w1, sel_b1, sel_w2, key_w, v_w1, v_b1, v_w2, v_b2
    const float* states = (const float*)d_in[1];
    const float* sel_w1 = (const float*)d_in[2];
    const float* sel_b1 = (const float*)d_in[3];
    const float* sel_w2 = (const float*)d_in[4];
    const float* key_w  = (const float*)d_in[5];
    const float* v_w1   = (const float*)d_in[6];
    const float* v_b1   = (const float*)d_in[7];
    const float* v_w2   = (const float*)d_in[8];
    const float* v_b2   = (const float*)d_in[9];
    float* out = (float*)d_out;

    cudaFuncSetAttribute(gemm_kernel, cudaFuncAttributeMaxDynamicSharedMemorySize, GEMM_SMEM);

    pack_transpose<<<dim3(SS / 32, 2, 5), dim3(32, 8)>>>(sel_w1, v_w1);
    pack_c<<<HHD, 256>>>(sel_w2, key_w, sel_b1, v_b1);
    gemm_kernel<<<BB / BM, 512, GEMM_SMEM>>>(states);
    m_kernel<<<BB / MR, 256>>>(v_w2, v_b2, out);
    attn_kernel<<<NB3, 256>>>(states, out);
    finalize_kernel<<<1, 256>>>(out);
}

// round 14
// speedup vs baseline: 1.6438x; 1.2083x over previous
#include <cuda_runtime.h>
#include <cuda_fp16.h>
#include <cstdint>

// Problem constants
#define BB   16384
#define AA   32
#define UU   64
#define SS   2048
#define EE   32
#define HYPD 64
#define HHD  4
#define NN   288      // H*HYP + E = 256 + 32
#define KKD  2048

#define NB3  (BB/8)   // attn kernel blocks (8 rows per block)

// ---------------- scratch (device globals; no allocation allowed) -------------
__device__ __half g_Sh[(size_t)BB * SS];   // fp16 copy of states (67MB)
__device__ __half g_Wh[NN * KKD];          // packed fp16 weights [n][k]
__device__ float g_bias[NN];               // concatenated biases
__device__ float g_H1[BB * NN];            // relu(states@W + bias)
__device__ float g_C[HHD * HYPD * UU];     // C[h][k][u]
__device__ float g_M[BB * 256];            // M[b][h*64+u]
__device__ float g_part[NB3 * 5];          // per-block partials: [mag, ent0..3]

__device__ __forceinline__ float warpsum(float v) {
    #pragma unroll
    for (int o = 16; o; o >>= 1) v += __shfl_xor_sync(0xffffffffu, v, o);
    return v;
}
__device__ __forceinline__ float warpmax(float v) {
    #pragma unroll
    for (int o = 16; o; o >>= 1) v = fmaxf(v, __shfl_xor_sync(0xffffffffu, v, o));
    return v;
}

__device__ __forceinline__ uint32_t smem_u32(const void* p) {
    return (uint32_t)__cvta_generic_to_shared(p);
}
__device__ __forceinline__ void cp_async16(uint32_t dst, const void* src) {
    asm volatile("cp.async.ca.shared.global [%0], [%1], 16;\n" :: "r"(dst), "l"(src));
}
__device__ __forceinline__ void cp_commit() {
    asm volatile("cp.async.commit_group;\n");
}
template <int N>
__device__ __forceinline__ void cp_wait() {
    asm volatile("cp.async.wait_group %0;\n" :: "n"(N));
}

// ---------------- kernel 0: states fp32 -> fp16 -------------------------------
__global__ __launch_bounds__(256)
void convert_states(const float* __restrict__ states) {
    size_t i = (size_t)blockIdx.x * 256 + threadIdx.x;   // 4 floats per thread
    float4 v = ((const float4*)states)[i];
    __half2 h0 = __floats2half2_rn(v.x, v.y);
    __half2 h1 = __floats2half2_rn(v.z, v.w);
    uint2 o;
    o.x = *reinterpret_cast<unsigned*>(&h0);
    o.y = *reinterpret_cast<unsigned*>(&h1);
    reinterpret_cast<uint2*>(g_Sh)[i] = o;
}

// ---------------- kernel 0a: coalesced weight pack via smem transpose ---------
__global__ __launch_bounds__(256)
void pack_transpose(const float* __restrict__ sel_w1,
                    const float* __restrict__ v_w1) {
    __shared__ float tile[32][33];
    const int z  = blockIdx.z;
    const int k0 = blockIdx.x * 32;
    const int j0 = blockIdx.y * 32;
    const int tx = threadIdx.x, ty = threadIdx.y;  // 32 x 8

    if (z == 4 && blockIdx.y != 0) return;

    if (z < 4) {
        const float* src = sel_w1 + (size_t)z * SS * HYPD;
        #pragma unroll
        for (int i = 0; i < 32; i += 8)
            tile[ty + i][tx] = src[(size_t)(k0 + ty + i) * HYPD + j0 + tx];
        __syncthreads();
        #pragma unroll
        for (int i = 0; i < 32; i += 8)
            g_Wh[(size_t)(z * 64 + j0 + ty + i) * KKD + k0 + tx] =
                __float2half_rn(tile[tx][ty + i]);
    } else {
        #pragma unroll
        for (int i = 0; i < 32; i += 8)
            tile[ty + i][tx] = v_w1[(size_t)(k0 + ty + i) * EE + tx];
        __syncthreads();
        #pragma unroll
        for (int i = 0; i < 32; i += 8)
            g_Wh[(size_t)(256 + ty + i) * KKD + k0 + tx] =
                __float2half_rn(tile[tx][ty + i]);
    }
}

// ---------------- kernel 0b: C[h] = sel_w2[h] @ key_w[h]^T, plus bias ---------
__global__ __launch_bounds__(256)
void pack_c(const float* __restrict__ sel_w2, const float* __restrict__ key_w,
            const float* __restrict__ sel_b1, const float* __restrict__ v_b1) {
    __shared__ float sw2[HYPD * EE];   // [k][e]
    __shared__ float kw[UU * EE];      // [u][e]
    const int h = blockIdx.x;
    const int t = threadIdx.x;

    if (h == 0) {
        for (int i = t; i < NN; i += 256)
            g_bias[i] = (i < 256) ? sel_b1[i] : v_b1[i - 256];
    }

    for (int i = t; i < HYPD * EE; i += 256) sw2[i] = sel_w2[h * HYPD * EE + i];
    for (int i = t; i < UU * EE; i += 256)   kw[i]  = key_w[h * UU * EE + i];
    __syncthreads();

    for (int o = t; o < HYPD * UU; o += 256) {
        int k = o >> 6, u = o & 63;
        float s = 0.f;
        #pragma unroll
        for (int e = 0; e < EE; e++) s += sw2[k * EE + e] * kw[u * EE + e];
        g_C[h * HYPD * UU + o] = s;
    }
}

// ---------------- kernel 1: GEMM [16384,2048]x[2048,288] fp16 m16n8k16 --------
// fp16 mantissa == tf32 mantissa (10 bits), fp32 accumulate: same accuracy as
// the tf32 path, half the mma instructions, half the smem fragment traffic.
#define BM 128
#define BKC 64          // k per tile (halves)
#define HS  72          // smem row stride in halves (144B)
#define STAGES 3
#define A_STG (BM * HS)     // 9216 halves (18432 B)
#define B_STG (NN * HS)     // 20736 halves (41472 B)
#define STG_H (A_STG + B_STG)
#define GEMM_SMEM (STAGES * STG_H * 2)   // 179712 bytes

__global__ __launch_bounds__(512, 1)
void gemm_kernel() {
    extern __shared__ __half smh[];
    __half* As = smh;
    __half* Bs = smh + STAGES * A_STG;

    const int t    = threadIdx.x;
    const int lane = t & 31;
    const int warp = t >> 5;
    const int wM   = warp & 3;
    const int wN   = warp >> 2;
    const int grp  = lane >> 2;
    const int tid4 = lane & 3;
    const int rowBase = blockIdx.x * BM;

    float acc[2][9][4];
    #pragma unroll
    for (int i = 0; i < 2; i++)
        #pragma unroll
        for (int j = 0; j < 9; j++)
            #pragma unroll
            for (int c = 0; c < 4; c++) acc[i][j][c] = 0.f;

    // stage loader: A 1024 chunks of 16B(=8 halves), B 2304 chunks
    auto load_stage = [&](int s, int k0) {
        {
            uint32_t dstA = smem_u32(As + s * A_STG);
            #pragma unroll
            for (int r = 0; r < 2; r++) {
                int c = t + r * 512;               // 0..1023
                int row = c >> 3, c4 = c & 7;
                cp_async16(dstA + (uint32_t)(row * 144 + c4 * 16),
                           g_Sh + (size_t)(rowBase + row) * KKD + k0 + c4 * 8);
            }
        }
        {
            uint32_t dstB = smem_u32(Bs + s * B_STG);
            for (int c = t; c < NN * 8; c += 512) {
                int row = c >> 3, c4 = c & 7;
                cp_async16(dstB + (uint32_t)(row * 144 + c4 * 16),
                           g_Wh + (size_t)row * KKD + k0 + c4 * 8);
            }
        }
        cp_commit();
    };

    load_stage(0, 0);
    load_stage(1, BKC);

    const int NITER = KKD / BKC;           // 32
    for (int it = 0; it < NITER; ++it) {
        const int cur = it % STAGES;
        if (it < NITER - 1) cp_wait<1>(); else cp_wait<0>();
        __syncthreads();

        if (it + STAGES - 1 < NITER)
            load_stage((it + 2) % STAGES, (it + 2) * BKC);

        const __half* Ab = As + cur * A_STG;
        const __half* Bb = Bs + cur * B_STG;
        #pragma unroll
        for (int kk = 0; kk < BKC; kk += 16) {
            uint32_t af[2][4];
            #pragma unroll
            for (int mt = 0; mt < 2; mt++) {
                int m0 = wM * 32 + mt * 16 + grp;
                af[mt][0] = *(const uint32_t*)(Ab + m0 * HS + kk + tid4 * 2);
                af[mt][1] = *(const uint32_t*)(Ab + (m0 + 8) * HS + kk + tid4 * 2);
                af[mt][2] = *(const uint32_t*)(Ab + m0 * HS + kk + 8 + tid4 * 2);
                af[mt][3] = *(const uint32_t*)(Ab + (m0 + 8) * HS + kk + 8 + tid4 * 2);
            }
            #pragma unroll
            for (int nt = 0; nt < 9; nt++) {
                int n0 = wN * 72 + nt * 8 + grp;
                uint32_t b0 = *(const uint32_t*)(Bb + n0 * HS + kk + tid4 * 2);
                uint32_t b1 = *(const uint32_t*)(Bb + n0 * HS + kk + 8 + tid4 * 2);
                #pragma unroll
                for (int mt = 0; mt < 2; mt++) {
                    asm volatile(
                        "mma.sync.aligned.m16n8k16.row.col.f32.f16.f16.f32 "
                        "{%0,%1,%2,%3}, {%4,%5,%6,%7}, {%8,%9}, {%0,%1,%2,%3};\n"
                        : "+f"(acc[mt][nt][0]), "+f"(acc[mt][nt][1]),
                          "+f"(acc[mt][nt][2]), "+f"(acc[mt][nt][3])
                        : "r"(af[mt][0]), "r"(af[mt][1]),
                          "r"(af[mt][2]), "r"(af[mt][3]),
                          "r"(b0), "r"(b1));
                }
            }
        }
    }

    // ---- epilogue: bias + relu -> g_H1 (accumulator layout same as tf32) ----
    #pragma unroll
    for (int mt = 0; mt < 2; mt++) {
        int r0 = rowBase + wM * 32 + mt * 16 + grp;
        #pragma unroll
        for (int nt = 0; nt < 9; nt++) {
            int c0 = wN * 72 + nt * 8 + tid4 * 2;
            float b0 = g_bias[c0], b1 = g_bias[c0 + 1];
            g_H1[(size_t)r0 * NN + c0]           = fmaxf(acc[mt][nt][0] + b0, 0.f);
            g_H1[(size_t)r0 * NN + c0 + 1]       = fmaxf(acc[mt][nt][1] + b1, 0.f);
            g_H1[(size_t)(r0 + 8) * NN + c0]     = fmaxf(acc[mt][nt][2] + b0, 0.f);
            g_H1[(size_t)(r0 + 8) * NN + c0 + 1] = fmaxf(acc[mt][nt][3] + b1, 0.f);
        }
    }
}

// ---------------- kernel 1.5: M = H1 @ blockdiag(C), register-resident C ------
#define MR   64    // rows per block  -> 256 blocks
#define MCH  8     // rows per chunk
#define NCHK (MR / MCH)
__global__ __launch_bounds__(256)
void m_kernel(const float* __restrict__ v_w2,
              const float* __restrict__ v_b2,
              float* __restrict__ out) {
    __shared__ float hs[2][MCH][NN];   // 18432 B
    __shared__ float vw2s[32];

    const int t = threadIdx.x;
    const int b0 = blockIdx.x * MR;
    const int h = t >> 6;
    const int u = t & 63;

    float creg[64];
    {
        const float* cp = g_C + h * HYPD * UU + u;
        #pragma unroll
        for (int k = 0; k < 64; k++) creg[k] = cp[k * UU];
    }
    if (t < 32) vw2s[t] = v_w2[t];
    const float vb2 = v_b2[0];

    auto load_chunk = [&](int s, int r0) {
        uint32_t dst = smem_u32(&hs[s][0][0]);
        for (int c = t; c < MCH * 72; c += 256) {
            int r = c / 72, q = c - r * 72;
            cp_async16(dst + (uint32_t)(r * NN + q * 4) * 4,
                       g_H1 + (size_t)(b0 + r0 + r) * NN + q * 4);
        }
        cp_commit();
    };

    load_chunk(0, 0);
    __syncthreads();

    for (int ch = 0; ch < NCHK; ch++) {
        const int cur = ch & 1;
        cp_wait<0>();
        __syncthreads();

        if (ch + 1 < NCHK) load_chunk(cur ^ 1, (ch + 1) * MCH);

        #pragma unroll
        for (int g = 0; g < 2; g++) {
            const float* h0 = &hs[cur][g * 4 + 0][h * 64];
            const float* h1 = &hs[cur][g * 4 + 1][h * 64];
            const float* h2 = &hs[cur][g * 4 + 2][h * 64];
            const float* h3 = &hs[cur][g * 4 + 3][h * 64];
            float a0 = 0.f, a1 = 0.f, a2 = 0.f, a3 = 0.f;
            #pragma unroll
            for (int k = 0; k < 64; k++) {
                float cv = creg[k];
                a0 += h0[k] * cv;
                a1 += h1[k] * cv;
                a2 += h2[k] * cv;
                a3 += h3[k] * cv;
            }
            const size_t r = (size_t)(b0 + ch * MCH + g * 4);
            g_M[(r + 0) * 256 + t] = a0;
            g_M[(r + 1) * 256 + t] = a1;
            g_M[(r + 2) * 256 + t] = a2;
            g_M[(r + 3) * 256 + t] = a3;
        }

        if (t < MCH) {
            float s = 0.f;
            const float* hr = &hs[cur][t][256];
            #pragma unroll
            for (int j = 0; j < 32; j++) s += hr[j] * vw2s[j];
            out[(size_t)BB * AA + b0 + ch * MCH + t] = s + vb2;
        }
    }
}

// ---------------- kernel 2: logits -> softmax -> outputs ----------------------
// One warp per batch row. lane owns u in {2*lane, 2*lane+1}: states read as
// half2, m as float2 -> half the load instructions vs scalar.
__global__ __launch_bounds__(256)
void attn_kernel(float* __restrict__ out) {
    __shared__ float spart[8][5];

    const int t = threadIdx.x, lane = t & 31, w = t >> 5;
    const int b = blockIdx.x * 8 + w;

    float m0[4], m1[4];
    const float* mrow = g_M + (size_t)b * 256;
    #pragma unroll
    for (int h = 0; h < 4; h++) {
        float2 mv = *(const float2*)(mrow + h * 64 + 2 * lane);
        m0[h] = mv.x; m1[h] = mv.y;
    }

    const __half* srow = g_Sh + (size_t)b * SS;
    float v0[32], v1[32];
    #pragma unroll
    for (int a = 0; a < 32; a++) {
        __half2 hv = *(const __half2*)(srow + a * 64 + 2 * lane);
        float2 f = __half22float2(hv);
        v0[a] = f.x; v1[a] = f.y;
    }

    float lg[4];
    #pragma unroll
    for (int h = 0; h < 4; h++) {
        float vals[32];
        #pragma unroll
        for (int a = 0; a < 32; a++)
            vals[a] = v0[a] * m0[h] + v1[a] * m1[h];
        #pragma unroll
        for (int m = 16; m >= 1; m >>= 1) {
            #pragma unroll
            for (int jj = 0; jj < m; jj++) {
                float lo = vals[jj], hi = vals[jj + m];
                float send = (lane & m) ? lo : hi;
                float recv = __shfl_xor_sync(0xffffffffu, send, m);
                vals[jj] = ((lane & m) ? hi : lo) + recv;
            }
        }
        lg[h] = vals[0];
    }

    const float invsq = 0.17677669529663687f;  // 1/sqrt(32)
    float ha = 0.f, mag = 0.f;
    float entp[4];
    #pragma unroll
    for (int h = 0; h < 4; h++) {
        mag += lg[h] * lg[h];
        float z = lg[h] * invsq;
        float mx = warpmax(z);
        float e = __expf(z - mx);
        float ssum = warpsum(e);
        float wgt = e / ssum;
        ha += wgt;
        entp[h] = warpsum(wgt * __logf(wgt + 1e-8f));
    }
    mag = warpsum(mag);

    out[(size_t)b * AA + lane] = ha;  // head_attend

    if (lane == 0) {
        spart[w][0] = mag;
        #pragma unroll
        for (int h = 0; h < 4; h++) spart[w][1 + h] = entp[h];
    }
    __syncthreads();
    if (t == 0) {
        float acc[5] = {0, 0, 0, 0, 0};
        for (int ww = 0; ww < 8; ww++)
            #pragma unroll
            for (int c = 0; c < 5; c++) acc[c] += spart[ww][c];
        #pragma unroll
        for (int c = 0; c < 5; c++) g_part[blockIdx.x * 5 + c] = acc[c];
    }
}

// ---------------- kernel 3: deterministic finalize ----------------------------
__global__ __launch_bounds__(256)
void finalize_kernel(float* __restrict__ out) {
    __shared__ float red[8][5];
    const int t = threadIdx.x, lane = t & 31, w = t >> 5;
    float acc[5] = {0, 0, 0, 0, 0};
    for (int j = t; j < NB3; j += 256) {
        #pragma unroll
        for (int c = 0; c < 5; c++) acc[c] += g_part[j * 5 + c];
    }
    #pragma unroll
    for (int c = 0; c < 5; c++) acc[c] = warpsum(acc[c]);
    if (lane == 0)
        #pragma unroll
        for (int c = 0; c < 5; c++) red[w][c] = acc[c];
    __syncthreads();
    if (t == 0) {
        float fin[5] = {0, 0, 0, 0, 0};
        #pragma unroll
        for (int ww = 0; ww < 8; ww++)
            #pragma unroll
            for (int c = 0; c < 5; c++) fin[c] += red[ww][c];
        out[(size_t)BB * AA + BB] = 1e-3f * fin[0] / (float)((size_t)BB * AA);
        #pragma unroll
        for (int c = 1; c < 5; c++)
            out[(size_t)BB * AA + BB + c] = -fin[c] / (float)BB;
    }
}

// ---------------- launch ------------------------------------------------------
extern "C" void kernel_launch(void* const* d_in, const int* in_sizes, int n_in,
                              void* d_out, int out_size) {
    (void)in_sizes; (void)n_in; (void)out_size;
    // metadata order: agent_qs, states, sel_w1, sel_b1, sel_w2, key_w, v_w1, v_b1, v_w2, v_b2
    const float* states = (const float*)d_in[1];
    const float* sel_w1 = (const float*)d_in[2];
    const float* sel_b1 = (const float*)d_in[3];
    const float* sel_w2 = (const float*)d_in[4];
    const float* key_w  = (const float*)d_in[5];
    const float* v_w1   = (const float*)d_in[6];
    const float* v_b1   = (const float*)d_in[7];
    const float* v_w2   = (const float*)d_in[8];
    const float* v_b2   = (const float*)d_in[9];
    float* out = (float*)d_out;

    cudaFuncSetAttribute(gemm_kernel, cudaFuncAttributeMaxDynamicSharedMemorySize, GEMM_SMEM);

    convert_states<<<(BB * SS / 4) / 256, 256>>>(states);
    pack_transpose<<<dim3(SS / 32, 2, 5), dim3(32, 8)>>>(sel_w1, v_w1);
    pack_c<<<HHD, 256>>>(sel_w2, key_w, sel_b1, v_b1);
    gemm_kernel<<<BB / BM, 512, GEMM_SMEM>>>();
    m_kernel<<<BB / MR, 256>>>(v_w2, v_b2, out);
    attn_kernel<<<NB3, 256>>>(out);
    finalize_kernel<<<1, 256>>>(out);
}

// round 15
// speedup vs baseline: 1.7484x; 1.0636x over previous
#include <cuda_runtime.h>
#include <cuda_fp16.h>
#include <cstdint>

// Problem constants
#define BB   16384
#define AA   32
#define UU   64
#define SS   2048
#define EE   32
#define HYPD 64
#define HHD  4
#define NN   288      // H*HYP + E = 256 + 32
#define KKD  2048

#define NB3  (BB/8)   // attn kernel blocks (8 rows per block)

// ---------------- scratch (device globals; no allocation allowed) -------------
__device__ __half g_Sh[(size_t)BB * SS];   // fp16 copy of states (67MB)
__device__ __half g_Wh[NN * KKD];          // packed fp16 weights [n][k]
__device__ float g_bias[NN];               // concatenated biases
__device__ float g_H1[BB * NN];            // relu(states@W + bias)
__device__ float g_C[HHD * HYPD * UU];     // C[h][k][u]
__device__ float g_M[BB * 256];            // M[b][h*64+u]
__device__ float g_part[NB3 * 5];          // per-block partials: [mag, ent0..3]

__device__ __forceinline__ float warpsum(float v) {
    #pragma unroll
    for (int o = 16; o; o >>= 1) v += __shfl_xor_sync(0xffffffffu, v, o);
    return v;
}
__device__ __forceinline__ float warpmax(float v) {
    #pragma unroll
    for (int o = 16; o; o >>= 1) v = fmaxf(v, __shfl_xor_sync(0xffffffffu, v, o));
    return v;
}

__device__ __forceinline__ uint32_t smem_u32(const void* p) {
    return (uint32_t)__cvta_generic_to_shared(p);
}
__device__ __forceinline__ void cp_async16(uint32_t dst, const void* src) {
    asm volatile("cp.async.ca.shared.global [%0], [%1], 16;\n" :: "r"(dst), "l"(src));
}
__device__ __forceinline__ void cp_commit() {
    asm volatile("cp.async.commit_group;\n");
}
template <int N>
__device__ __forceinline__ void cp_wait() {
    asm volatile("cp.async.wait_group %0;\n" :: "n"(N));
}
__device__ __forceinline__ void ldsm_x4(uint32_t& r0, uint32_t& r1,
                                        uint32_t& r2, uint32_t& r3, uint32_t addr) {
    asm volatile("ldmatrix.sync.aligned.m8n8.x4.shared.b16 {%0,%1,%2,%3}, [%4];"
                 : "=r"(r0), "=r"(r1), "=r"(r2), "=r"(r3) : "r"(addr));
}
__device__ __forceinline__ void ldsm_x2(uint32_t& r0, uint32_t& r1, uint32_t addr) {
    asm volatile("ldmatrix.sync.aligned.m8n8.x2.shared.b16 {%0,%1}, [%2];"
                 : "=r"(r0), "=r"(r1) : "r"(addr));
}

// ---------------- kernel 0: states fp32 -> fp16 -------------------------------
__global__ __launch_bounds__(256)
void convert_states(const float* __restrict__ states) {
    size_t i = (size_t)blockIdx.x * 256 + threadIdx.x;   // 4 floats per thread
    float4 v = ((const float4*)states)[i];
    __half2 h0 = __floats2half2_rn(v.x, v.y);
    __half2 h1 = __floats2half2_rn(v.z, v.w);
    uint2 o;
    o.x = *reinterpret_cast<unsigned*>(&h0);
    o.y = *reinterpret_cast<unsigned*>(&h1);
    reinterpret_cast<uint2*>(g_Sh)[i] = o;
}

// ---------------- kernel 0a: coalesced weight pack via smem transpose ---------
__global__ __launch_bounds__(256)
void pack_transpose(const float* __restrict__ sel_w1,
                    const float* __restrict__ v_w1) {
    __shared__ float tile[32][33];
    const int z  = blockIdx.z;
    const int k0 = blockIdx.x * 32;
    const int j0 = blockIdx.y * 32;
    const int tx = threadIdx.x, ty = threadIdx.y;  // 32 x 8

    if (z == 4 && blockIdx.y != 0) return;

    if (z < 4) {
        const float* src = sel_w1 + (size_t)z * SS * HYPD;
        #pragma unroll
        for (int i = 0; i < 32; i += 8)
            tile[ty + i][tx] = src[(size_t)(k0 + ty + i) * HYPD + j0 + tx];
        __syncthreads();
        #pragma unroll
        for (int i = 0; i < 32; i += 8)
            g_Wh[(size_t)(z * 64 + j0 + ty + i) * KKD + k0 + tx] =
                __float2half_rn(tile[tx][ty + i]);
    } else {
        #pragma unroll
        for (int i = 0; i < 32; i += 8)
            tile[ty + i][tx] = v_w1[(size_t)(k0 + ty + i) * EE + tx];
        __syncthreads();
        #pragma unroll
        for (int i = 0; i < 32; i += 8)
            g_Wh[(size_t)(256 + ty + i) * KKD + k0 + tx] =
                __float2half_rn(tile[tx][ty + i]);
    }
}

// ---------------- kernel 0b: C[h] = sel_w2[h] @ key_w[h]^T, plus bias ---------
__global__ __launch_bounds__(256)
void pack_c(const float* __restrict__ sel_w2, const float* __restrict__ key_w,
            const float* __restrict__ sel_b1, const float* __restrict__ v_b1) {
    __shared__ float sw2[HYPD * EE];   // [k][e]
    __shared__ float kw[UU * EE];      // [u][e]
    const int h = blockIdx.x;
    const int t = threadIdx.x;

    if (h == 0) {
        for (int i = t; i < NN; i += 256)
            g_bias[i] = (i < 256) ? sel_b1[i] : v_b1[i - 256];
    }

    for (int i = t; i < HYPD * EE; i += 256) sw2[i] = sel_w2[h * HYPD * EE + i];
    for (int i = t; i < UU * EE; i += 256)   kw[i]  = key_w[h * UU * EE + i];
    __syncthreads();

    for (int o = t; o < HYPD * UU; o += 256) {
        int k = o >> 6, u = o & 63;
        float s = 0.f;
        #pragma unroll
        for (int e = 0; e < EE; e++) s += sw2[k * EE + e] * kw[u * EE + e];
        g_C[h * HYPD * UU + o] = s;
    }
}

// ---------------- kernel 1: GEMM [16384,2048]x[2048,288] fp16 m16n8k16 --------
// Fragment loads via ldmatrix: 7 LDSM per k16-step vs 26 scalar LDS.
#define BM 128
#define BKC 64          // k per tile (halves)
#define HS  72          // smem row stride in halves (144B; rows land on distinct bank groups)
#define STAGES 3
#define A_STG (BM * HS)     // 9216 halves (18432 B)
#define B_STG (NN * HS)     // 20736 halves (41472 B)
#define STG_H (A_STG + B_STG)
#define GEMM_SMEM (STAGES * STG_H * 2)   // 179712 bytes

__global__ __launch_bounds__(512, 1)
void gemm_kernel() {
    extern __shared__ __half smh[];
    __half* As = smh;
    __half* Bs = smh + STAGES * A_STG;

    const int t    = threadIdx.x;
    const int lane = t & 31;
    const int warp = t >> 5;
    const int wM   = warp & 3;
    const int wN   = warp >> 2;
    const int grp  = lane >> 2;
    const int tid4 = lane & 3;
    const int rowBase = blockIdx.x * BM;

    float acc[2][9][4];
    #pragma unroll
    for (int i = 0; i < 2; i++)
        #pragma unroll
        for (int j = 0; j < 9; j++)
            #pragma unroll
            for (int c = 0; c < 4; c++) acc[i][j][c] = 0.f;

    // ldmatrix per-thread address offsets (in halves, within a stage)
    // A x4 (per mt): row = wM*32 + mt*16 + (lane&15), col = 8*(lane>>4)
    const int aRowOff0 = (wM * 32 + 0  + (lane & 15)) * HS + 8 * (lane >> 4);
    const int aRowOff1 = (wM * 32 + 16 + (lane & 15)) * HS + 8 * (lane >> 4);
    // B x4 (per nt-pair p): row = wN*72 + p*16 + (lane&7) + 8*(lane>>4),
    //                       col = 8*((lane>>3)&1)
    const int bPairOff = (wN * 72 + (lane & 7) + 8 * (lane >> 4)) * HS
                         + 8 * ((lane >> 3) & 1);
    // B x2 (nt=8): row = wN*72 + 64 + (lane&7), col = 8*((lane>>3)&1)
    const int bLastOff = (wN * 72 + 64 + (lane & 7)) * HS + 8 * ((lane >> 3) & 1);

    // stage loader: A 1024 chunks of 16B(=8 halves), B 2304 chunks
    auto load_stage = [&](int s, int k0) {
        {
            uint32_t dstA = smem_u32(As + s * A_STG);
            #pragma unroll
            for (int r = 0; r < 2; r++) {
                int c = t + r * 512;               // 0..1023
                int row = c >> 3, c4 = c & 7;
                cp_async16(dstA + (uint32_t)(row * 144 + c4 * 16),
                           g_Sh + (size_t)(rowBase + row) * KKD + k0 + c4 * 8);
            }
        }
        {
            uint32_t dstB = smem_u32(Bs + s * B_STG);
            for (int c = t; c < NN * 8; c += 512) {
                int row = c >> 3, c4 = c & 7;
                cp_async16(dstB + (uint32_t)(row * 144 + c4 * 16),
                           g_Wh + (size_t)row * KKD + k0 + c4 * 8);
            }
        }
        cp_commit();
    };

    load_stage(0, 0);
    load_stage(1, BKC);

    const int NITER = KKD / BKC;           // 32
    for (int it = 0; it < NITER; ++it) {
        const int cur = it % STAGES;
        if (it < NITER - 1) cp_wait<1>(); else cp_wait<0>();
        __syncthreads();

        if (it + STAGES - 1 < NITER)
            load_stage((it + 2) % STAGES, (it + 2) * BKC);

        const uint32_t aB = smem_u32(As + cur * A_STG) ;
        const uint32_t bB = smem_u32(Bs + cur * B_STG);
        const uint32_t a0addr = aB + (uint32_t)aRowOff0 * 2;
        const uint32_t a1addr = aB + (uint32_t)aRowOff1 * 2;
        const uint32_t bpaddr = bB + (uint32_t)bPairOff * 2;
        const uint32_t bladdr = bB + (uint32_t)bLastOff * 2;

        #pragma unroll
        for (int kk = 0; kk < BKC; kk += 16) {
            const uint32_t kb = (uint32_t)kk * 2;   // byte offset along k
            uint32_t af[2][4];
            ldsm_x4(af[0][0], af[0][1], af[0][2], af[0][3], a0addr + kb);
            ldsm_x4(af[1][0], af[1][1], af[1][2], af[1][3], a1addr + kb);

            #pragma unroll
            for (int p = 0; p < 4; p++) {
                uint32_t b0a, b1a, b0b, b1b;
                ldsm_x4(b0a, b1a, b0b, b1b, bpaddr + (uint32_t)(p * 16 * HS) * 2 + kb);
                #pragma unroll
                for (int mt = 0; mt < 2; mt++) {
                    asm volatile(
                        "mma.sync.aligned.m16n8k16.row.col.f32.f16.f16.f32 "
                        "{%0,%1,%2,%3}, {%4,%5,%6,%7}, {%8,%9}, {%0,%1,%2,%3};\n"
                        : "+f"(acc[mt][2 * p][0]), "+f"(acc[mt][2 * p][1]),
                          "+f"(acc[mt][2 * p][2]), "+f"(acc[mt][2 * p][3])
                        : "r"(af[mt][0]), "r"(af[mt][1]),
                          "r"(af[mt][2]), "r"(af[mt][3]),
                          "r"(b0a), "r"(b1a));
                    asm volatile(
                        "mma.sync.aligned.m16n8k16.row.col.f32.f16.f16.f32 "
                        "{%0,%1,%2,%3}, {%4,%5,%6,%7}, {%8,%9}, {%0,%1,%2,%3};\n"
                        : "+f"(acc[mt][2 * p + 1][0]), "+f"(acc[mt][2 * p + 1][1]),
                          "+f"(acc[mt][2 * p + 1][2]), "+f"(acc[mt][2 * p + 1][3])
                        : "r"(af[mt][0]), "r"(af[mt][1]),
                          "r"(af[mt][2]), "r"(af[mt][3]),
                          "r"(b0b), "r"(b1b));
                }
            }
            {
                uint32_t b0, b1;
                ldsm_x2(b0, b1, bladdr + kb);
                #pragma unroll
                for (int mt = 0; mt < 2; mt++) {
                    asm volatile(
                        "mma.sync.aligned.m16n8k16.row.col.f32.f16.f16.f32 "
                        "{%0,%1,%2,%3}, {%4,%5,%6,%7}, {%8,%9}, {%0,%1,%2,%3};\n"
                        : "+f"(acc[mt][8][0]), "+f"(acc[mt][8][1]),
                          "+f"(acc[mt][8][2]), "+f"(acc[mt][8][3])
                        : "r"(af[mt][0]), "r"(af[mt][1]),
                          "r"(af[mt][2]), "r"(af[mt][3]),
                          "r"(b0), "r"(b1));
                }
            }
        }
    }

    // ---- epilogue: bias + relu -> g_H1 (fragment layout unchanged) ----
    #pragma unroll
    for (int mt = 0; mt < 2; mt++) {
        int r0 = rowBase + wM * 32 + mt * 16 + grp;
        #pragma unroll
        for (int nt = 0; nt < 9; nt++) {
            int c0 = wN * 72 + nt * 8 + tid4 * 2;
            float b0 = g_bias[c0], b1 = g_bias[c0 + 1];
            g_H1[(size_t)r0 * NN + c0]           = fmaxf(acc[mt][nt][0] + b0, 0.f);
            g_H1[(size_t)r0 * NN + c0 + 1]       = fmaxf(acc[mt][nt][1] + b1, 0.f);
            g_H1[(size_t)(r0 + 8) * NN + c0]     = fmaxf(acc[mt][nt][2] + b0, 0.f);
            g_H1[(size_t)(r0 + 8) * NN + c0 + 1] = fmaxf(acc[mt][nt][3] + b1, 0.f);
        }
    }
}

// ---------------- kernel 1.5: M = H1 @ blockdiag(C), register-resident C ------
#define MR   64    // rows per block  -> 256 blocks
#define MCH  8     // rows per chunk
#define NCHK (MR / MCH)
__global__ __launch_bounds__(256)
void m_kernel(const float* __restrict__ v_w2,
              const float* __restrict__ v_b2,
              float* __restrict__ out) {
    __shared__ float hs[2][MCH][NN];   // 18432 B
    __shared__ float vw2s[32];

    const int t = threadIdx.x;
    const int b0 = blockIdx.x * MR;
    const int h = t >> 6;
    const int u = t & 63;

    float creg[64];
    {
        const float* cp = g_C + h * HYPD * UU + u;
        #pragma unroll
        for (int k = 0; k < 64; k++) creg[k] = cp[k * UU];
    }
    if (t < 32) vw2s[t] = v_w2[t];
    const float vb2 = v_b2[0];

    auto load_chunk = [&](int s, int r0) {
        uint32_t dst = smem_u32(&hs[s][0][0]);
        for (int c = t; c < MCH * 72; c += 256) {
            int r = c / 72, q = c - r * 72;
            cp_async16(dst + (uint32_t)(r * NN + q * 4) * 4,
                       g_H1 + (size_t)(b0 + r0 + r) * NN + q * 4);
        }
        cp_commit();
    };

    load_chunk(0, 0);
    __syncthreads();

    for (int ch = 0; ch < NCHK; ch++) {
        const int cur = ch & 1;
        cp_wait<0>();
        __syncthreads();

        if (ch + 1 < NCHK) load_chunk(cur ^ 1, (ch + 1) * MCH);

        #pragma unroll
        for (int g = 0; g < 2; g++) {
            const float* h0 = &hs[cur][g * 4 + 0][h * 64];
            const float* h1 = &hs[cur][g * 4 + 1][h * 64];
            const float* h2 = &hs[cur][g * 4 + 2][h * 64];
            const float* h3 = &hs[cur][g * 4 + 3][h * 64];
            float a0 = 0.f, a1 = 0.f, a2 = 0.f, a3 = 0.f;
            #pragma unroll
            for (int k = 0; k < 64; k++) {
                float cv = creg[k];
                a0 += h0[k] * cv;
                a1 += h1[k] * cv;
                a2 += h2[k] * cv;
                a3 += h3[k] * cv;
            }
            const size_t r = (size_t)(b0 + ch * MCH + g * 4);
            g_M[(r + 0) * 256 + t] = a0;
            g_M[(r + 1) * 256 + t] = a1;
            g_M[(r + 2) * 256 + t] = a2;
            g_M[(r + 3) * 256 + t] = a3;
        }

        if (t < MCH) {
            float s = 0.f;
            const float* hr = &hs[cur][t][256];
            #pragma unroll
            for (int j = 0; j < 32; j++) s += hr[j] * vw2s[j];
            out[(size_t)BB * AA + b0 + ch * MCH + t] = s + vb2;
        }
    }
}

// ---------------- kernel 2: logits -> softmax -> outputs ----------------------
__global__ __launch_bounds__(256)
void attn_kernel(float* __restrict__ out) {
    __shared__ float spart[8][5];

    const int t = threadIdx.x, lane = t & 31, w = t >> 5;
    const int b = blockIdx.x * 8 + w;

    float m0[4], m1[4];
    const float* mrow = g_M + (size_t)b * 256;
    #pragma unroll
    for (int h = 0; h < 4; h++) {
        float2 mv = *(const float2*)(mrow + h * 64 + 2 * lane);
        m0[h] = mv.x; m1[h] = mv.y;
    }

    const __half* srow = g_Sh + (size_t)b * SS;
    float v0[32], v1[32];
    #pragma unroll
    for (int a = 0; a < 32; a++) {
        __half2 hv = *(const __half2*)(srow + a * 64 + 2 * lane);
        float2 f = __half22float2(hv);
        v0[a] = f.x; v1[a] = f.y;
    }

    float lg[4];
    #pragma unroll
    for (int h = 0; h < 4; h++) {
        float vals[32];
        #pragma unroll
        for (int a = 0; a < 32; a++)
            vals[a] = v0[a] * m0[h] + v1[a] * m1[h];
        #pragma unroll
        for (int m = 16; m >= 1; m >>= 1) {
            #pragma unroll
            for (int jj = 0; jj < m; jj++) {
                float lo = vals[jj], hi = vals[jj + m];
                float send = (lane & m) ? lo : hi;
                float recv = __shfl_xor_sync(0xffffffffu, send, m);
                vals[jj] = ((lane & m) ? hi : lo) + recv;
            }
        }
        lg[h] = vals[0];
    }

    const float invsq = 0.17677669529663687f;  // 1/sqrt(32)
    float ha = 0.f, mag = 0.f;
    float entp[4];
    #pragma unroll
    for (int h = 0; h < 4; h++) {
        mag += lg[h] * lg[h];
        float z = lg[h] * invsq;
        float mx = warpmax(z);
        float e = __expf(z - mx);
        float ssum = warpsum(e);
        float wgt = e / ssum;
        ha += wgt;
        entp[h] = warpsum(wgt * __logf(wgt + 1e-8f));
    }
    mag = warpsum(mag);

    out[(size_t)b * AA + lane] = ha;  // head_attend

    if (lane == 0) {
        spart[w][0] = mag;
        #pragma unroll
        for (int h = 0; h < 4; h++) spart[w][1 + h] = entp[h];
    }
    __syncthreads();
    if (t == 0) {
        float acc[5] = {0, 0, 0, 0, 0};
        for (int ww = 0; ww < 8; ww++)
            #pragma unroll
            for (int c = 0; c < 5; c++) acc[c] += spart[ww][c];
        #pragma unroll
        for (int c = 0; c < 5; c++) g_part[blockIdx.x * 5 + c] = acc[c];
    }
}

// ---------------- kernel 3: deterministic finalize ----------------------------
__global__ __launch_bounds__(256)
void finalize_kernel(float* __restrict__ out) {
    __shared__ float red[8][5];
    const int t = threadIdx.x, lane = t & 31, w = t >> 5;
    float acc[5] = {0, 0, 0, 0, 0};
    for (int j = t; j < NB3; j += 256) {
        #pragma unroll
        for (int c = 0; c < 5; c++) acc[c] += g_part[j * 5 + c];
    }
    #pragma unroll
    for (int c = 0; c < 5; c++) acc[c] = warpsum(acc[c]);
    if (lane == 0)
        #pragma unroll
        for (int c = 0; c < 5; c++) red[w][c] = acc[c];
    __syncthreads();
    if (t == 0) {
        float fin[5] = {0, 0, 0, 0, 0};
        #pragma unroll
        for (int ww = 0; ww < 8; ww++)
            #pragma unroll
            for (int c = 0; c < 5; c++) fin[c] += red[ww][c];
        out[(size_t)BB * AA + BB] = 1e-3f * fin[0] / (float)((size_t)BB * AA);
        #pragma unroll
        for (int c = 1; c < 5; c++)
            out[(size_t)BB * AA + BB + c] = -fin[c] / (float)BB;
    }
}

// ---------------- launch ------------------------------------------------------
extern "C" void kernel_launch(void* const* d_in, const int* in_sizes, int n_in,
                              void* d_out, int out_size) {
    (void)in_sizes; (void)n_in; (void)out_size;
    // metadata order: agent_qs, states, sel_w1, sel_b1, sel_w2, key_w, v_w1, v_b1, v_w2, v_b2
    const float* states = (const float*)d_in[1];
    const float* sel_w1 = (const float*)d_in[2];
    const float* sel_b1 = (const float*)d_in[3];
    const float* sel_w2 = (const float*)d_in[4];
    const float* key_w  = (const float*)d_in[5];
    const float* v_w1   = (const float*)d_in[6];
    const float* v_b1   = (const float*)d_in[7];
    const float* v_w2   = (const float*)d_in[8];
    const float* v_b2   = (const float*)d_in[9];
    float* out = (float*)d_out;

    cudaFuncSetAttribute(gemm_kernel, cudaFuncAttributeMaxDynamicSharedMemorySize, GEMM_SMEM);

    convert_states<<<(BB * SS / 4) / 256, 256>>>(states);
    pack_transpose<<<dim3(SS / 32, 2, 5), dim3(32, 8)>>>(sel_w1, v_w1);
    pack_c<<<HHD, 256>>>(sel_w2, key_w, sel_b1, v_b1);
    gemm_kernel<<<BB / BM, 512, GEMM_SMEM>>>();
    m_kernel<<<BB / MR, 256>>>(v_w2, v_b2, out);
    attn_kernel<<<NB3, 256>>>(out);
    finalize_kernel<<<1, 256>>>(out);
}

// round 17
// speedup vs baseline: 1.7694x; 1.0121x over previous
#include <cuda_runtime.h>
#include <cuda_fp16.h>
#include <cstdint>

// Problem constants
#define BB   16384
#define AA   32
#define UU   64
#define SS   2048
#define EE   32
#define HYPD 64
#define HHD  4
#define NN   288      // H*HYP + E = 256 + 32
#define KKD  2048

#define NB3  (BB/8)   // attn kernel blocks (8 rows per block)

// ---------------- scratch (device globals; no allocation allowed) -------------
__device__ __half g_Wh[NN * KKD];          // packed fp16 weights [n][k]
__device__ float g_bias[NN];               // concatenated biases
__device__ float g_H1[BB * NN];            // relu(states@W + bias)
__device__ float g_C[HHD * HYPD * UU];     // C[h][k][u]
__device__ float g_M[BB * 256];            // M[b][h*64+u]
__device__ float g_part[NB3 * 5];          // per-block partials: [mag, ent0..3]

__device__ __forceinline__ float warpsum(float v) {
    #pragma unroll
    for (int o = 16; o; o >>= 1) v += __shfl_xor_sync(0xffffffffu, v, o);
    return v;
}
__device__ __forceinline__ float warpmax(float v) {
    #pragma unroll
    for (int o = 16; o; o >>= 1) v = fmaxf(v, __shfl_xor_sync(0xffffffffu, v, o));
    return v;
}

__device__ __forceinline__ uint32_t smem_u32(const void* p) {
    return (uint32_t)__cvta_generic_to_shared(p);
}
__device__ __forceinline__ void cp_async16(uint32_t dst, const void* src) {
    asm volatile("cp.async.ca.shared.global [%0], [%1], 16;\n" :: "r"(dst), "l"(src));
}
__device__ __forceinline__ void cp_commit() {
    asm volatile("cp.async.commit_group;\n");
}
template <int N>
__device__ __forceinline__ void cp_wait() {
    asm volatile("cp.async.wait_group %0;\n" :: "n"(N));
}
__device__ __forceinline__ void ldsm_x4(uint32_t& r0, uint32_t& r1,
                                        uint32_t& r2, uint32_t& r3, uint32_t addr) {
    asm volatile("ldmatrix.sync.aligned.m8n8.x4.shared.b16 {%0,%1,%2,%3}, [%4];"
                 : "=r"(r0), "=r"(r1), "=r"(r2), "=r"(r3) : "r"(addr));
}
__device__ __forceinline__ void ldsm_x2(uint32_t& r0, uint32_t& r1, uint32_t addr) {
    asm volatile("ldmatrix.sync.aligned.m8n8.x2.shared.b16 {%0,%1}, [%2];"
                 : "=r"(r0), "=r"(r1) : "r"(addr));
}

// ---------------- kernel 0a: coalesced weight pack via smem transpose ---------
__global__ __launch_bounds__(256)
void pack_transpose(const float* __restrict__ sel_w1,
                    const float* __restrict__ v_w1) {
    __shared__ float tile[32][33];
    const int z  = blockIdx.z;
    const int k0 = blockIdx.x * 32;
    const int j0 = blockIdx.y * 32;
    const int tx = threadIdx.x, ty = threadIdx.y;  // 32 x 8

    if (z == 4 && blockIdx.y != 0) return;

    if (z < 4) {
        const float* src = sel_w1 + (size_t)z * SS * HYPD;
        #pragma unroll
        for (int i = 0; i < 32; i += 8)
            tile[ty + i][tx] = src[(size_t)(k0 + ty + i) * HYPD + j0 + tx];
        __syncthreads();
        #pragma unroll
        for (int i = 0; i < 32; i += 8)
            g_Wh[(size_t)(z * 64 + j0 + ty + i) * KKD + k0 + tx] =
                __float2half_rn(tile[tx][ty + i]);
    } else {
        #pragma unroll
        for (int i = 0; i < 32; i += 8)
            tile[ty + i][tx] = v_w1[(size_t)(k0 + ty + i) * EE + tx];
        __syncthreads();
        #pragma unroll
        for (int i = 0; i < 32; i += 8)
            g_Wh[(size_t)(256 + ty + i) * KKD + k0 + tx] =
                __float2half_rn(tile[tx][ty + i]);
    }
}

// ---------------- kernel 0b: C[h] = sel_w2[h] @ key_w[h]^T, plus bias ---------
__global__ __launch_bounds__(256)
void pack_c(const float* __restrict__ sel_w2, const float* __restrict__ key_w,
            const float* __restrict__ sel_b1, const float* __restrict__ v_b1) {
    __shared__ float sw2[HYPD * EE];   // [k][e]
    __shared__ float kw[UU * EE];      // [u][e]
    const int h = blockIdx.x;
    const int t = threadIdx.x;

    if (h == 0) {
        for (int i = t; i < NN; i += 256)
            g_bias[i] = (i < 256) ? sel_b1[i] : v_b1[i - 256];
    }

    for (int i = t; i < HYPD * EE; i += 256) sw2[i] = sel_w2[h * HYPD * EE + i];
    for (int i = t; i < UU * EE; i += 256)   kw[i]  = key_w[h * UU * EE + i];
    __syncthreads();

    for (int o = t; o < HYPD * UU; o += 256) {
        int k = o >> 6, u = o & 63;
        float s = 0.f;
        #pragma unroll
        for (int e = 0; e < EE; e++) s += sw2[k * EE + e] * kw[u * EE + e];
        g_C[h * HYPD * UU + o] = s;
    }
}

// ---------------- kernel 1: GEMM [16384,2048]x[2048,288] fp16 m16n8k16 --------
#define BM 128
#define BKC 64
#define HS  72
#define STAGES 3
#define A_STG (BM * HS)
#define B_STG (NN * HS)
#define STG_H (A_STG + B_STG)
#define GEMM_SMEM (STAGES * STG_H * 2)   // 179712 bytes

__global__ __launch_bounds__(512, 1)
void gemm_kernel(const float* __restrict__ states) {
    extern __shared__ __half smh[];
    __half* As = smh;
    __half* Bs = smh + STAGES * A_STG;

    const int t    = threadIdx.x;
    const int lane = t & 31;
    const int warp = t >> 5;
    const int wM   = warp & 3;
    const int wN   = warp >> 2;
    const int grp  = lane >> 2;
    const int tid4 = lane & 3;
    const int rowBase = blockIdx.x * BM;

    float acc[2][9][4];
    #pragma unroll
    for (int i = 0; i < 2; i++)
        #pragma unroll
        for (int j = 0; j < 9; j++)
            #pragma unroll
            for (int c = 0; c < 4; c++) acc[i][j][c] = 0.f;

    const int aRowOff0 = (wM * 32 + 0  + (lane & 15)) * HS + 8 * (lane >> 4);
    const int aRowOff1 = (wM * 32 + 16 + (lane & 15)) * HS + 8 * (lane >> 4);
    const int bPairOff = (wN * 72 + (lane & 7) + 8 * (lane >> 4)) * HS
                         + 8 * ((lane >> 3) & 1);
    const int bLastOff = (wN * 72 + 64 + (lane & 7)) * HS + 8 * ((lane >> 3) & 1);

    auto load_stage = [&](int s, int k0) {
        {
            __half* dstA = As + s * A_STG;
            #pragma unroll
            for (int r = 0; r < 2; r++) {
                int c = t + r * 512;
                int row = c >> 3, c4 = c & 7;
                const float4* src = (const float4*)(states +
                    (size_t)(rowBase + row) * KKD + k0 + c4 * 8);
                float4 f0 = src[0], f1 = src[1];
                __half2 h0 = __floats2half2_rn(f0.x, f0.y);
                __half2 h1 = __floats2half2_rn(f0.z, f0.w);
                __half2 h2 = __floats2half2_rn(f1.x, f1.y);
                __half2 h3 = __floats2half2_rn(f1.z, f1.w);
                uint4 o;
                o.x = *reinterpret_cast<unsigned*>(&h0);
                o.y = *reinterpret_cast<unsigned*>(&h1);
                o.z = *reinterpret_cast<unsigned*>(&h2);
                o.w = *reinterpret_cast<unsigned*>(&h3);
                *reinterpret_cast<uint4*>(dstA + row * HS + c4 * 8) = o;
            }
        }
        {
            uint32_t dstB = smem_u32(Bs + s * B_STG);
            for (int c = t; c < NN * 8; c += 512) {
                int row = c >> 3, c4 = c & 7;
                cp_async16(dstB + (uint32_t)(row * 144 + c4 * 16),
                           g_Wh + (size_t)row * KKD + k0 + c4 * 8);
            }
        }
        cp_commit();
    };

    load_stage(0, 0);
    load_stage(1, BKC);

    const int NITER = KKD / BKC;           // 32
    for (int it = 0; it < NITER; ++it) {
        const int cur = it % STAGES;
        if (it < NITER - 1) cp_wait<1>(); else cp_wait<0>();
        __syncthreads();

        if (it + STAGES - 1 < NITER)
            load_stage((it + 2) % STAGES, (it + 2) * BKC);

        const uint32_t aB = smem_u32(As + cur * A_STG);
        const uint32_t bB = smem_u32(Bs + cur * B_STG);
        const uint32_t a0addr = aB + (uint32_t)aRowOff0 * 2;
        const uint32_t a1addr = aB + (uint32_t)aRowOff1 * 2;
        const uint32_t bpaddr = bB + (uint32_t)bPairOff * 2;
        const uint32_t bladdr = bB + (uint32_t)bLastOff * 2;

        #pragma unroll
        for (int kk = 0; kk < BKC; kk += 16) {
            const uint32_t kb = (uint32_t)kk * 2;
            uint32_t af[2][4];
            ldsm_x4(af[0][0], af[0][1], af[0][2], af[0][3], a0addr + kb);
            ldsm_x4(af[1][0], af[1][1], af[1][2], af[1][3], a1addr + kb);

            #pragma unroll
            for (int p = 0; p < 4; p++) {
                uint32_t b0a, b1a, b0b, b1b;
                ldsm_x4(b0a, b1a, b0b, b1b, bpaddr + (uint32_t)(p * 16 * HS) * 2 + kb);
                #pragma unroll
                for (int mt = 0; mt < 2; mt++) {
                    asm volatile(
                        "mma.sync.aligned.m16n8k16.row.col.f32.f16.f16.f32 "
                        "{%0,%1,%2,%3}, {%4,%5,%6,%7}, {%8,%9}, {%0,%1,%2,%3};\n"
                        : "+f"(acc[mt][2 * p][0]), "+f"(acc[mt][2 * p][1]),
                          "+f"(acc[mt][2 * p][2]), "+f"(acc[mt][2 * p][3])
                        : "r"(af[mt][0]), "r"(af[mt][1]),
                          "r"(af[mt][2]), "r"(af[mt][3]),
                          "r"(b0a), "r"(b1a));
                    asm volatile(
                        "mma.sync.aligned.m16n8k16.row.col.f32.f16.f16.f32 "
                        "{%0,%1,%2,%3}, {%4,%5,%6,%7}, {%8,%9}, {%0,%1,%2,%3};\n"
                        : "+f"(acc[mt][2 * p + 1][0]), "+f"(acc[mt][2 * p + 1][1]),
                          "+f"(acc[mt][2 * p + 1][2]), "+f"(acc[mt][2 * p + 1][3])
                        : "r"(af[mt][0]), "r"(af[mt][1]),
                          "r"(af[mt][2]), "r"(af[mt][3]),
                          "r"(b0b), "r"(b1b));
                }
            }
            {
                uint32_t b0, b1;
                ldsm_x2(b0, b1, bladdr + kb);
                #pragma unroll
                for (int mt = 0; mt < 2; mt++) {
                    asm volatile(
                        "mma.sync.aligned.m16n8k16.row.col.f32.f16.f16.f32 "
                        "{%0,%1,%2,%3}, {%4,%5,%6,%7}, {%8,%9}, {%0,%1,%2,%3};\n"
                        : "+f"(acc[mt][8][0]), "+f"(acc[mt][8][1]),
                          "+f"(acc[mt][8][2]), "+f"(acc[mt][8][3])
                        : "r"(af[mt][0]), "r"(af[mt][1]),
                          "r"(af[mt][2]), "r"(af[mt][3]),
                          "r"(b0), "r"(b1));
                }
            }
        }
    }

    #pragma unroll
    for (int mt = 0; mt < 2; mt++) {
        int r0 = rowBase + wM * 32 + mt * 16 + grp;
        #pragma unroll
        for (int nt = 0; nt < 9; nt++) {
            int c0 = wN * 72 + nt * 8 + tid4 * 2;
            float b0 = g_bias[c0], b1 = g_bias[c0 + 1];
            g_H1[(size_t)r0 * NN + c0]           = fmaxf(acc[mt][nt][0] + b0, 0.f);
            g_H1[(size_t)r0 * NN + c0 + 1]       = fmaxf(acc[mt][nt][1] + b1, 0.f);
            g_H1[(size_t)(r0 + 8) * NN + c0]     = fmaxf(acc[mt][nt][2] + b0, 0.f);
            g_H1[(size_t)(r0 + 8) * NN + c0 + 1] = fmaxf(acc[mt][nt][3] + b1, 0.f);
        }
    }
}

// ---------------- kernel 1.5: M = H1 @ blockdiag(C), register-resident C ------
#define MR   64
#define MCH  8
#define NCHK (MR / MCH)
__global__ __launch_bounds__(256)
void m_kernel(const float* __restrict__ v_w2,
              const float* __restrict__ v_b2,
              float* __restrict__ out) {
    __shared__ float hs[2][MCH][NN];
    __shared__ float vw2s[32];

    const int t = threadIdx.x;
    const int b0 = blockIdx.x * MR;
    const int h = t >> 6;
    const int u = t & 63;

    float creg[64];
    {
        const float* cp = g_C + h * HYPD * UU + u;
        #pragma unroll
        for (int k = 0; k < 64; k++) creg[k] = cp[k * UU];
    }
    if (t < 32) vw2s[t] = v_w2[t];
    const float vb2 = v_b2[0];

    auto load_chunk = [&](int s, int r0) {
        uint32_t dst = smem_u32(&hs[s][0][0]);
        for (int c = t; c < MCH * 72; c += 256) {
            int r = c / 72, q = c - r * 72;
            cp_async16(dst + (uint32_t)(r * NN + q * 4) * 4,
                       g_H1 + (size_t)(b0 + r0 + r) * NN + q * 4);
        }
        cp_commit();
    };

    load_chunk(0, 0);
    __syncthreads();

    for (int ch = 0; ch < NCHK; ch++) {
        const int cur = ch & 1;
        cp_wait<0>();
        __syncthreads();

        if (ch + 1 < NCHK) load_chunk(cur ^ 1, (ch + 1) * MCH);

        #pragma unroll
        for (int g = 0; g < 2; g++) {
            const float* h0 = &hs[cur][g * 4 + 0][h * 64];
            const float* h1 = &hs[cur][g * 4 + 1][h * 64];
            const float* h2 = &hs[cur][g * 4 + 2][h * 64];
            const float* h3 = &hs[cur][g * 4 + 3][h * 64];
            float a0 = 0.f, a1 = 0.f, a2 = 0.f, a3 = 0.f;
            #pragma unroll
            for (int k = 0; k < 64; k++) {
                float cv = creg[k];
                a0 += h0[k] * cv;
                a1 += h1[k] * cv;
                a2 += h2[k] * cv;
                a3 += h3[k] * cv;
            }
            const size_t r = (size_t)(b0 + ch * MCH + g * 4);
            g_M[(r + 0) * 256 + t] = a0;
            g_M[(r + 1) * 256 + t] = a1;
            g_M[(r + 2) * 256 + t] = a2;
            g_M[(r + 3) * 256 + t] = a3;
        }

        if (t < MCH) {
            float s = 0.f;
            const float* hr = &hs[cur][t][256];
            #pragma unroll
            for (int j = 0; j < 32; j++) s += hr[j] * vw2s[j];
            out[(size_t)BB * AA + b0 + ch * MCH + t] = s + vb2;
        }
    }
}

// ---------------- kernel 2: logits -> softmax -> outputs ----------------------
__global__ __launch_bounds__(256)
void attn_kernel(const float* __restrict__ states,
                 float* __restrict__ out) {
    __shared__ float spart[8][5];

    const int t = threadIdx.x, lane = t & 31, w = t >> 5;
    const int b = blockIdx.x * 8 + w;

    float m0[4], m1[4];
    const float* mrow = g_M + (size_t)b * 256;
    #pragma unroll
    for (int h = 0; h < 4; h++) {
        float2 mv = *(const float2*)(mrow + h * 64 + 2 * lane);
        m0[h] = mv.x; m1[h] = mv.y;
    }

    const float* srow = states + (size_t)b * SS;
    float v0[32], v1[32];
    #pragma unroll
    for (int a = 0; a < 32; a++) {
        float2 sv = *(const float2*)(srow + a * 64 + 2 * lane);
        v0[a] = sv.x; v1[a] = sv.y;
    }

    float lg[4];
    #pragma unroll
    for (int h = 0; h < 4; h++) {
        float vals[32];
        #pragma unroll
        for (int a = 0; a < 32; a++)
            vals[a] = v0[a] * m0[h] + v1[a] * m1[h];
        #pragma unroll
        for (int m = 16; m >= 1; m >>= 1) {
            #pragma unroll
            for (int jj = 0; jj < m; jj++) {
                float lo = vals[jj], hi = vals[jj + m];
                float send = (lane & m) ? lo : hi;
                float recv = __shfl_xor_sync(0xffffffffu, send, m);
                vals[jj] = ((lane & m) ? hi : lo) + recv;
            }
        }
        lg[h] = vals[0];
    }

    const float invsq = 0.17677669529663687f;  // 1/sqrt(32)
    float ha = 0.f, mag = 0.f;
    float entp[4];
    #pragma unroll
    for (int h = 0; h < 4; h++) {
        mag += lg[h] * lg[h];
        float z = lg[h] * invsq;
        float mx = warpmax(z);
        float e = __expf(z - mx);
        float ssum = warpsum(e);
        float wgt = e / ssum;
        ha += wgt;
        entp[h] = warpsum(wgt * __logf(wgt + 1e-8f));
    }
    mag = warpsum(mag);

    out[(size_t)b * AA + lane] = ha;  // head_attend

    if (lane == 0) {
        spart[w][0] = mag;
        #pragma unroll
        for (int h = 0; h < 4; h++) spart[w][1 + h] = entp[h];
    }
    __syncthreads();
    if (t == 0) {
        float acc[5] = {0, 0, 0, 0, 0};
        for (int ww = 0; ww < 8; ww++)
            #pragma unroll
            for (int c = 0; c < 5; c++) acc[c] += spart[ww][c];
        #pragma unroll
        for (int c = 0; c < 5; c++) g_part[blockIdx.x * 5 + c] = acc[c];
    }
}

// ---------------- kernel 3: deterministic finalize ----------------------------
__global__ __launch_bounds__(256)
void finalize_kernel(float* __restrict__ out) {
    __shared__ float red[8][5];
    const int t = threadIdx.x, lane = t & 31, w = t >> 5;
    float acc[5] = {0, 0, 0, 0, 0};
    for (int j = t; j < NB3; j += 256) {
        #pragma unroll
        for (int c = 0; c < 5; c++) acc[c] += g_part[j * 5 + c];
    }
    #pragma unroll
    for (int c = 0; c < 5; c++) acc[c] = warpsum(acc[c]);
    if (lane == 0)
        #pragma unroll
        for (int c = 0; c < 5; c++) red[w][c] = acc[c];
    __syncthreads();
    if (t == 0) {
        float fin[5] = {0, 0, 0, 0, 0};
        #pragma unroll
        for (int ww = 0; ww < 8; ww++)
            #pragma unroll
            for (int c = 0; c < 5; c++) fin[c] += red[ww][c];
        out[(size_t)BB * AA + BB] = 1e-3f * fin[0] / (float)((size_t)BB * AA);
        #pragma unroll
        for (int c = 1; c < 5; c++)
            out[(size_t)BB * AA + BB + c] = -fin[c] / (float)BB;
    }
}

// ---------------- launch ------------------------------------------------------
extern "C" void kernel_launch(void* const* d_in, const int* in_sizes, int n_in,
                              void* d_out, int out_size) {
    (void)in_sizes; (void)n_in; (void)out_size;
    // metadata order: agent_qs, states, sel_w1, sel_b1, sel_w2, key_w, v_w1, v_b1, v_w2, v_b2
    const float* states = (const float*)d_in[1];
    const float* sel_w1 = (const float*)d_in[2];
    const float* sel_b1 = (const float*)d_in[3];
    const float* sel_w2 = (const float*)d_in[4];
    const float* key_w  = (const float*)d_in[5];
    const float* v_w1   = (const float*)d_in[6];
    const float* v_b1   = (const float*)d_in[7];
    const float* v_w2   = (const float*)d_in[8];
    const float* v_b2   = (const float*)d_in[9];
    float* out = (float*)d_out;

    cudaFuncSetAttribute(gemm_kernel, cudaFuncAttributeMaxDynamicSharedMemorySize, GEMM_SMEM);

    pack_transpose<<<dim3(SS / 32, 2, 5), dim3(32, 8)>>>(sel_w1, v_w1);
    pack_c<<<HHD, 256>>>(sel_w2, key_w, sel_b1, v_b1);
    gemm_kernel<<<BB / BM, 512, GEMM_SMEM>>>(states);
    m_kernel<<<BB / MR, 256>>>(v_w2, v_b2, out);
    attn_kernel<<<NB3, 256>>>(states, out);
    finalize_kernel<<<1, 256>>>(out);
}